// round 3
// baseline (speedup 1.0000x reference)
#include <cuda_runtime.h>

// Problem constants
#define S_LEN   512
#define HDIM    1024
#define BATCH   64
#define IDIM    1024
#define M_TOT   (BATCH * S_LEN)          // 32768
#define OUT_TAIL (BATCH * S_LEN * HDIM)  // offset of h_last region in d_out

// ====================================================================
// Kernel 1: input projection GEMM (unchanged from R2 — ~FFMA-bound)
//   C[m,n] = sum_i A[m,i] * Wih[n,i] + (bih[n] + bhh[n])
// ====================================================================
__global__ void __launch_bounds__(256) xproj_kernel(
    const float* __restrict__ A,
    const float* __restrict__ W,
    const float* __restrict__ bih,
    const float* __restrict__ bhh,
    float* __restrict__ C)
{
    __shared__ float As[16][132];
    __shared__ float Bs[16][132];

    const int tid = threadIdx.x;
    const int tx  = tid & 15;
    const int ty  = tid >> 4;
    const int m0  = blockIdx.y * 128;
    const int n0  = blockIdx.x * 128;

    float acc[8][8];
#pragma unroll
    for (int i = 0; i < 8; i++)
#pragma unroll
        for (int j = 0; j < 8; j++) acc[i][j] = 0.0f;

    const float4* A4 = (const float4*)A;
    const float4* W4 = (const float4*)W;

    for (int k0 = 0; k0 < IDIM; k0 += 16) {
        const int kq = k0 >> 2;
#pragma unroll
        for (int q = 0; q < 2; q++) {
            int f  = q * 256 + tid;
            int r  = f >> 2;
            int c4 = f & 3;
            float4 av = A4[(size_t)(m0 + r) * 256 + kq + c4];
            As[c4 * 4 + 0][r] = av.x;
            As[c4 * 4 + 1][r] = av.y;
            As[c4 * 4 + 2][r] = av.z;
            As[c4 * 4 + 3][r] = av.w;
            float4 bv = W4[(size_t)(n0 + r) * 256 + kq + c4];
            Bs[c4 * 4 + 0][r] = bv.x;
            Bs[c4 * 4 + 1][r] = bv.y;
            Bs[c4 * 4 + 2][r] = bv.z;
            Bs[c4 * 4 + 3][r] = bv.w;
        }
        __syncthreads();

#pragma unroll
        for (int kk = 0; kk < 16; kk++) {
            float ra[8], rb[8];
            *(float4*)&ra[0] = *(const float4*)&As[kk][ty * 4];
            *(float4*)&ra[4] = *(const float4*)&As[kk][64 + ty * 4];
            *(float4*)&rb[0] = *(const float4*)&Bs[kk][tx * 4];
            *(float4*)&rb[4] = *(const float4*)&Bs[kk][64 + tx * 4];
#pragma unroll
            for (int i = 0; i < 8; i++)
#pragma unroll
                for (int j = 0; j < 8; j++)
                    acc[i][j] = fmaf(ra[i], rb[j], acc[i][j]);
        }
        __syncthreads();
    }

    float bsum[8];
#pragma unroll
    for (int j = 0; j < 8; j++) {
        int n = n0 + ((j < 4) ? (tx * 4 + j) : (64 + tx * 4 + (j - 4)));
        bsum[j] = bih[n] + bhh[n];
    }
#pragma unroll
    for (int i = 0; i < 8; i++) {
        int m = m0 + ((i < 4) ? (ty * 4 + i) : (64 + ty * 4 + (i - 4)));
        float4 v0, v1;
        v0.x = acc[i][0] + bsum[0]; v0.y = acc[i][1] + bsum[1];
        v0.z = acc[i][2] + bsum[2]; v0.w = acc[i][3] + bsum[3];
        v1.x = acc[i][4] + bsum[4]; v1.y = acc[i][5] + bsum[5];
        v1.z = acc[i][6] + bsum[6]; v1.w = acc[i][7] + bsum[7];
        *(float4*)&C[(size_t)m * HDIM + n0 + tx * 4]      = v0;
        *(float4*)&C[(size_t)m * HDIM + n0 + 64 + tx * 4] = v1;
    }
}

// ====================================================================
// Kernel 2: persistent recurrence, v2.
//   128 CTAs = 4 groups x 32 CTAs, 512 threads each (16 warps).
//   Per CTA tile: 16 batch x 32 neurons, 1 output/thread.
//   h_{t-1} read straight from d_out (where step t-1 stored it) via
//   cp.async.cg (L2 path, no L1 staleness), double-buffered by k-chunk.
//   xp for this step prefetched before the dot loop.
// ====================================================================
#define WSTR 1028
#define REC_SMEM_BYTES ((32 + 16) * WSTR * 4)

__device__ unsigned g_cnt[4];
__device__ volatile unsigned g_phase[4];

__device__ __forceinline__ unsigned smem_u32(const void* p) {
    unsigned a;
    asm("{ .reg .u64 t; cvta.to.shared.u64 t, %1; cvt.u32.u64 %0, t; }"
        : "=r"(a) : "l"(p));
    return a;
}
__device__ __forceinline__ void cp16(unsigned saddr, const void* g) {
    asm volatile("cp.async.cg.shared.global [%0], [%1], 16;\n"
                 :: "r"(saddr), "l"(g) : "memory");
}
__device__ __forceinline__ void cp_commit() {
    asm volatile("cp.async.commit_group;\n" ::: "memory");
}
template <int N>
__device__ __forceinline__ void cp_wait() {
    asm volatile("cp.async.wait_group %0;\n" :: "n"(N) : "memory");
}

__global__ void __launch_bounds__(512, 1) rec_kernel(
    const float* __restrict__ h0,
    const float* __restrict__ Whh,
    float* out)
{
    extern __shared__ float sm[];
    float* Wsm = sm;                 // [32][WSTR]
    float* hsm = sm + 32 * WSTR;     // [16][WSTR]

    const int cta = blockIdx.x;
    const int grp = cta >> 5;        // 0..3 batch group
    const int gc  = cta & 31;        // 0..31 within group
    const int j0  = gc * 32;
    const int b0g = grp * 16;
    const int tid = threadIdx.x;
    const int warp = tid >> 5, lane = tid & 31;

    // output mapping: warp gives (j-block, b-block), lane gives (j, b)
    const int jl = (warp & 7) * 4 + (lane >> 3);   // 0..31
    const int bl = (warp >> 3) * 8 + (lane & 7);   // 0..15
    const int jglob = j0 + jl;
    const int bglob = b0g + bl;

    // ---- load W_hh rows [j0, j0+32) into SMEM once ----
    {
        const float4* W4 = (const float4*)Whh;
        for (int i = tid; i < 32 * 256; i += 512) {
            int r = i >> 8, c = i & 255;
            *(float4*)&Wsm[r * WSTR + c * 4] = W4[(size_t)(j0 + r) * 256 + c];
        }
    }

    const float* wp = Wsm + jl * WSTR;
    const float* hp = hsm + bl * WSTR;

    unsigned my_phase = 0;

    for (int t = 0; t < S_LEN; t++) {
        // ---- stage h_{t-1} (16 rows x 1024) via cp.async, 2 k-chunks ----
        // chunk c covers k in [c*512, c*512+512); 4 cp.async/thread/chunk
#pragma unroll
        for (int c = 0; c < 2; c++) {
#pragma unroll
            for (int q = 0; q < 4; q++) {
                int f  = q * 512 + tid;           // 0..2047
                int r  = f >> 7;                  // 0..15 (row)
                int kq = (f & 127) + c * 128;     // float4 index within row
                const float* gsrc = (t == 0)
                    ? (h0 + (size_t)(b0g + r) * HDIM + kq * 4)
                    : (out + ((size_t)(b0g + r) * S_LEN + (t - 1)) * HDIM + kq * 4);
                cp16(smem_u32(&hsm[r * WSTR + kq * 4]), gsrc);
            }
            cp_commit();
        }

        // ---- prefetch xp for this output (constant; hidden by dot loop) ----
        const size_t o = ((size_t)bglob * S_LEN + t) * HDIM + jglob;
        float x = out[o];

        float a0 = 0.0f, a1 = 0.0f;

        // chunk 0 ready
        cp_wait<1>();
        __syncthreads();
#pragma unroll 4
        for (int k = 0; k < 512; k += 8) {
            float4 w0 = *(const float4*)(wp + k);
            float4 hv0 = *(const float4*)(hp + k);
            float4 w1 = *(const float4*)(wp + k + 4);
            float4 hv1 = *(const float4*)(hp + k + 4);
            a0 = fmaf(w0.x, hv0.x, a0); a1 = fmaf(w1.x, hv1.x, a1);
            a0 = fmaf(w0.y, hv0.y, a0); a1 = fmaf(w1.y, hv1.y, a1);
            a0 = fmaf(w0.z, hv0.z, a0); a1 = fmaf(w1.z, hv1.z, a1);
            a0 = fmaf(w0.w, hv0.w, a0); a1 = fmaf(w1.w, hv1.w, a1);
        }

        // chunk 1 ready
        cp_wait<0>();
        __syncthreads();
#pragma unroll 4
        for (int k = 512; k < 1024; k += 8) {
            float4 w0 = *(const float4*)(wp + k);
            float4 hv0 = *(const float4*)(hp + k);
            float4 w1 = *(const float4*)(wp + k + 4);
            float4 hv1 = *(const float4*)(hp + k + 4);
            a0 = fmaf(w0.x, hv0.x, a0); a1 = fmaf(w1.x, hv1.x, a1);
            a0 = fmaf(w0.y, hv0.y, a0); a1 = fmaf(w1.y, hv1.y, a1);
            a0 = fmaf(w0.z, hv0.z, a0); a1 = fmaf(w1.z, hv1.z, a1);
            a0 = fmaf(w0.w, hv0.w, a0); a1 = fmaf(w1.w, hv1.w, a1);
        }

        // ---- relu + store (h_t lives in `out` itself) ----
        float hv = fmaxf(x + a0 + a1, 0.0f);
        out[o] = hv;
        if (t == S_LEN - 1) {
            out[OUT_TAIL + (size_t)bglob * HDIM + jglob] = hv;
        }

        // ---- group barrier (32 CTAs), sense-reversing (even count: replay-safe) ----
        __threadfence();   // publish this thread's store at gpu scope
        __syncthreads();
        if (tid == 0) {
            unsigned old = atomicAdd(&g_cnt[grp], 1u);
            if (old == 31u) {
                atomicExch(&g_cnt[grp], 0u);
                __threadfence();
                g_phase[grp] = my_phase ^ 1u;   // release the group
            } else {
                while (g_phase[grp] == my_phase) { __nanosleep(32); }
            }
            __threadfence();  // acquire
        }
        my_phase ^= 1u;
        __syncthreads();
    }
}

// ====================================================================
// Launch
// ====================================================================
extern "C" void kernel_launch(void* const* d_in, const int* in_sizes, int n_in,
                              void* d_out, int out_size)
{
    const float* inputs = (const float*)d_in[0];   // [64,512,1024]
    const float* h0     = (const float*)d_in[1];   // [1,64,1024]
    const float* wih    = (const float*)d_in[2];   // [1024,1024]
    const float* whh    = (const float*)d_in[3];   // [1024,1024]
    const float* bih    = (const float*)d_in[4];   // [1024]
    const float* bhh    = (const float*)d_in[5];   // [1024]
    float* out = (float*)d_out;

    dim3 g1(HDIM / 128, M_TOT / 128);   // (8, 256)
    xproj_kernel<<<g1, 256>>>(inputs, wih, bih, bhh, out);

    cudaFuncSetAttribute(rec_kernel, cudaFuncAttributeMaxDynamicSharedMemorySize,
                         REC_SMEM_BYTES);
    rec_kernel<<<128, 512, REC_SMEM_BYTES>>>(h0, whh, out);
}

// round 4
// speedup vs baseline: 1.3216x; 1.3216x over previous
#include <cuda_runtime.h>

// Problem constants
#define S_LEN   512
#define HDIM    1024
#define BATCH   64
#define IDIM    1024
#define M_TOT   (BATCH * S_LEN)          // 32768
#define OUT_TAIL (BATCH * S_LEN * HDIM)  // offset of h_last region in d_out

typedef unsigned long long u64;

// ---- packed f32x2 helpers (SASS FFMA2 path, PTX-only) ----
__device__ __forceinline__ u64 pack2(float lo, float hi) {
    u64 r;
    asm("mov.b64 %0, {%1, %2};" : "=l"(r) : "f"(lo), "f"(hi));
    return r;
}
__device__ __forceinline__ void unpack2(float& lo, float& hi, u64 v) {
    asm("mov.b64 {%0, %1}, %2;" : "=f"(lo), "=f"(hi) : "l"(v));
}
__device__ __forceinline__ void fma2(u64& d, u64 a, u64 b) {
    asm("fma.rn.f32x2 %0, %1, %2, %0;" : "+l"(d) : "l"(a), "l"(b));
}

// ====================================================================
// Kernel 1: input projection GEMM with f32x2 accumulation
//   C[m,n] = sum_i A[m,i] * Wih[n,i] + (bih[n] + bhh[n])
// ====================================================================
__global__ void __launch_bounds__(256) xproj_kernel(
    const float* __restrict__ A,
    const float* __restrict__ W,
    const float* __restrict__ bih,
    const float* __restrict__ bhh,
    float* __restrict__ C)
{
    __shared__ float As[16][132];
    __shared__ float Bs[16][132];

    const int tid = threadIdx.x;
    const int tx  = tid & 15;
    const int ty  = tid >> 4;
    const int m0  = blockIdx.y * 128;
    const int n0  = blockIdx.x * 128;

    // packed accumulators: acc2[i][p] holds cols pair p for row i
    u64 acc2[8][4];
#pragma unroll
    for (int i = 0; i < 8; i++)
#pragma unroll
        for (int p = 0; p < 4; p++) acc2[i][p] = 0ull;

    const float4* A4 = (const float4*)A;
    const float4* W4 = (const float4*)W;

    for (int k0 = 0; k0 < IDIM; k0 += 16) {
        const int kq = k0 >> 2;
#pragma unroll
        for (int q = 0; q < 2; q++) {
            int f  = q * 256 + tid;
            int r  = f >> 2;
            int c4 = f & 3;
            float4 av = A4[(size_t)(m0 + r) * 256 + kq + c4];
            As[c4 * 4 + 0][r] = av.x;
            As[c4 * 4 + 1][r] = av.y;
            As[c4 * 4 + 2][r] = av.z;
            As[c4 * 4 + 3][r] = av.w;
            float4 bv = W4[(size_t)(n0 + r) * 256 + kq + c4];
            Bs[c4 * 4 + 0][r] = bv.x;
            Bs[c4 * 4 + 1][r] = bv.y;
            Bs[c4 * 4 + 2][r] = bv.z;
            Bs[c4 * 4 + 3][r] = bv.w;
        }
        __syncthreads();

#pragma unroll
        for (int kk = 0; kk < 16; kk++) {
            float ra[8];
            *(float4*)&ra[0] = *(const float4*)&As[kk][ty * 4];
            *(float4*)&ra[4] = *(const float4*)&As[kk][64 + ty * 4];
            ulonglong2 rb0 = *(const ulonglong2*)&Bs[kk][tx * 4];      // cols (0,1),(2,3)
            ulonglong2 rb1 = *(const ulonglong2*)&Bs[kk][64 + tx * 4]; // cols (4,5),(6,7)
#pragma unroll
            for (int i = 0; i < 8; i++) {
                u64 rap = pack2(ra[i], ra[i]);
                fma2(acc2[i][0], rap, rb0.x);
                fma2(acc2[i][1], rap, rb0.y);
                fma2(acc2[i][2], rap, rb1.x);
                fma2(acc2[i][3], rap, rb1.y);
            }
        }
        __syncthreads();
    }

    float bsum[8];
#pragma unroll
    for (int j = 0; j < 8; j++) {
        int n = n0 + ((j < 4) ? (tx * 4 + j) : (64 + tx * 4 + (j - 4)));
        bsum[j] = bih[n] + bhh[n];
    }
#pragma unroll
    for (int i = 0; i < 8; i++) {
        int m = m0 + ((i < 4) ? (ty * 4 + i) : (64 + ty * 4 + (i - 4)));
        float c[8];
        unpack2(c[0], c[1], acc2[i][0]);
        unpack2(c[2], c[3], acc2[i][1]);
        unpack2(c[4], c[5], acc2[i][2]);
        unpack2(c[6], c[7], acc2[i][3]);
        float4 v0, v1;
        v0.x = c[0] + bsum[0]; v0.y = c[1] + bsum[1];
        v0.z = c[2] + bsum[2]; v0.w = c[3] + bsum[3];
        v1.x = c[4] + bsum[4]; v1.y = c[5] + bsum[5];
        v1.z = c[6] + bsum[6]; v1.w = c[7] + bsum[7];
        *(float4*)&C[(size_t)m * HDIM + n0 + tx * 4]      = v0;
        *(float4*)&C[(size_t)m * HDIM + n0 + 64 + tx * 4] = v1;
    }
}

// ====================================================================
// Kernel 2: persistent recurrence with f32x2 (R2 structure).
//   128 CTAs = 4 groups x 32 CTAs, 256 threads, 2 outputs/thread.
//   h_{t-1} read from `out` (written there at step t-1) via __ldcv.
// ====================================================================
#define WSTR 1028                       // padded row stride (floats); 16B-aligned rows
#define REC_SMEM_BYTES ((32 + 16) * WSTR * 4)

__device__ unsigned g_cnt[4];
__device__ volatile unsigned g_phase[4];

__global__ void __launch_bounds__(256, 1) rec_kernel(
    const float* __restrict__ h0,
    const float* __restrict__ Whh,
    float* out)
{
    extern __shared__ float sm[];
    float* Wsm = sm;                 // [32][WSTR]
    float* hsm = sm + 32 * WSTR;     // [16][WSTR]

    const int cta = blockIdx.x;
    const int grp = cta >> 5;        // 0..3 batch group
    const int gc  = cta & 31;        // 0..31 within group
    const int j0  = gc * 32;
    const int b0g = grp * 16;
    const int tid = threadIdx.x;

    // ---- load W_hh rows [j0, j0+32) into SMEM once ----
    {
        const float4* W4 = (const float4*)Whh;
        for (int i = tid; i < 32 * 256; i += 256) {
            int r = i >> 8, c = i & 255;
            *(float4*)&Wsm[r * WSTR + c * 4] = W4[(size_t)(j0 + r) * 256 + c];
        }
    }

    // ---- per-thread mapping (R2): 2 outputs (bg0,j), (bg0+1,j) ----
    const int w    = tid >> 5, l = tid & 31;
    const int jgrp = w & 3,  bgrp = w >> 2;
    const int jj   = l & 7,  bb   = l >> 3;
    const int jl   = jgrp * 8 + jj;          // 0..31
    const int bl   = bgrp * 8 + bb * 2;      // 0..14 even
    const int jglob = j0 + jl;
    const int bg0  = b0g + bl;
    const int bg1  = bg0 + 1;

    const ulonglong2* w2 = (const ulonglong2*)(Wsm + jl * WSTR);
    const ulonglong2* a2 = (const ulonglong2*)(hsm + bl * WSTR);
    const ulonglong2* b2 = (const ulonglong2*)(hsm + (bl + 1) * WSTR);

    unsigned my_phase = 0;

    for (int t = 0; t < S_LEN; t++) {
        // ---- stage h_{t-1} (16 rows x 1024 f32) into SMEM ----
        const float4* H4 = (t == 0)
            ? (const float4*)h0
            : (const float4*)(out + (size_t)(t - 1) * HDIM);
        // for t>0: row b's data at out[(b*S_LEN + (t-1))*HDIM] =
        //          base (t-1)*HDIM + b*S_LEN*HDIM
        const size_t rstride = (t == 0) ? 256u : (size_t)S_LEN * 256u;
#pragma unroll
        for (int q = 0; q < 16; q++) {
            int f = q * 256 + tid;            // 0..4095
            int r = f >> 8, c = f & 255;
            float4 v = __ldcv(&H4[(size_t)(b0g + r) * rstride + c]);
            *(float4*)&hsm[r * WSTR + c * 4] = v;
        }
        __syncthreads();

        // ---- prefetch xp (constant input term, staged in d_out) ----
        const size_t o0 = ((size_t)bg0 * S_LEN + t) * HDIM + jglob;
        const size_t o1 = ((size_t)bg1 * S_LEN + t) * HDIM + jglob;
        float x0 = out[o0], x1 = out[o1];

        // ---- packed dot products ----
        u64 acc0[4] = {0ull, 0ull, 0ull, 0ull};
        u64 acc1[4] = {0ull, 0ull, 0ull, 0ull};
#pragma unroll 4
        for (int q = 0; q < 64; q++) {        // 16 k per iter
            ulonglong2 wA = w2[4 * q + 0];
            ulonglong2 wB = w2[4 * q + 1];
            ulonglong2 wC = w2[4 * q + 2];
            ulonglong2 wD = w2[4 * q + 3];
            ulonglong2 aA = a2[4 * q + 0];
            ulonglong2 aB = a2[4 * q + 1];
            ulonglong2 aC = a2[4 * q + 2];
            ulonglong2 aD = a2[4 * q + 3];
            ulonglong2 bA = b2[4 * q + 0];
            ulonglong2 bB = b2[4 * q + 1];
            ulonglong2 bC = b2[4 * q + 2];
            ulonglong2 bD = b2[4 * q + 3];
            fma2(acc0[0], wA.x, aA.x);  fma2(acc1[0], wA.x, bA.x);
            fma2(acc0[1], wA.y, aA.y);  fma2(acc1[1], wA.y, bA.y);
            fma2(acc0[2], wB.x, aB.x);  fma2(acc1[2], wB.x, bB.x);
            fma2(acc0[3], wB.y, aB.y);  fma2(acc1[3], wB.y, bB.y);
            fma2(acc0[0], wC.x, aC.x);  fma2(acc1[0], wC.x, bC.x);
            fma2(acc0[1], wC.y, aC.y);  fma2(acc1[1], wC.y, bC.y);
            fma2(acc0[2], wD.x, aD.x);  fma2(acc1[2], wD.x, bD.x);
            fma2(acc0[3], wD.y, aD.y);  fma2(acc1[3], wD.y, bD.y);
        }

        // horizontal reduce
        float s0 = 0.0f, s1 = 0.0f;
#pragma unroll
        for (int p = 0; p < 4; p++) {
            float lo, hi;
            unpack2(lo, hi, acc0[p]); s0 += lo + hi;
            unpack2(lo, hi, acc1[p]); s1 += lo + hi;
        }

        float h0v = fmaxf(x0 + s0, 0.0f);
        float h1v = fmaxf(x1 + s1, 0.0f);
        out[o0] = h0v;
        out[o1] = h1v;
        if (t == S_LEN - 1) {
            out[OUT_TAIL + (size_t)bg0 * HDIM + jglob] = h0v;
            out[OUT_TAIL + (size_t)bg1 * HDIM + jglob] = h1v;
        }

        // ---- group barrier (32 CTAs), sense-reversing ----
        __syncthreads();
        if (tid == 0) {
            __threadfence();   // drain this SM's prior stores (post-sync)
            unsigned old = atomicAdd(&g_cnt[grp], 1u);
            if (old == 31u) {
                atomicExch(&g_cnt[grp], 0u);
                __threadfence();
                g_phase[grp] = my_phase ^ 1u;
            } else {
                while (g_phase[grp] == my_phase) { __nanosleep(32); }
            }
            __threadfence();   // acquire
        }
        my_phase ^= 1u;
        __syncthreads();
    }
}

// ====================================================================
// Launch
// ====================================================================
extern "C" void kernel_launch(void* const* d_in, const int* in_sizes, int n_in,
                              void* d_out, int out_size)
{
    const float* inputs = (const float*)d_in[0];   // [64,512,1024]
    const float* h0     = (const float*)d_in[1];   // [1,64,1024]
    const float* wih    = (const float*)d_in[2];   // [1024,1024]
    const float* whh    = (const float*)d_in[3];   // [1024,1024]
    const float* bih    = (const float*)d_in[4];   // [1024]
    const float* bhh    = (const float*)d_in[5];   // [1024]
    float* out = (float*)d_out;

    dim3 g1(HDIM / 128, M_TOT / 128);   // (8, 256)
    xproj_kernel<<<g1, 256>>>(inputs, wih, bih, bhh, out);

    cudaFuncSetAttribute(rec_kernel, cudaFuncAttributeMaxDynamicSharedMemorySize,
                         REC_SMEM_BYTES);
    rec_kernel<<<128, 256, REC_SMEM_BYTES>>>(h0, whh, out);
}

// round 5
// speedup vs baseline: 1.8885x; 1.4290x over previous
#include <cuda_runtime.h>

// Problem constants
#define S_LEN   512
#define HDIM    1024
#define BATCH   64
#define IDIM    1024
#define M_TOT   (BATCH * S_LEN)          // 32768
#define OUT_TAIL (BATCH * S_LEN * HDIM)  // offset of h_last region in d_out

typedef unsigned long long u64;

// ---- packed f32x2 helpers (SASS FFMA2 path, PTX-only) ----
__device__ __forceinline__ u64 pack2(float lo, float hi) {
    u64 r;
    asm("mov.b64 %0, {%1, %2};" : "=l"(r) : "f"(lo), "f"(hi));
    return r;
}
__device__ __forceinline__ void unpack2(float& lo, float& hi, u64 v) {
    asm("mov.b64 {%0, %1}, %2;" : "=f"(lo), "=f"(hi) : "l"(v));
}
__device__ __forceinline__ void fma2(u64& d, u64 a, u64 b) {
    asm("fma.rn.f32x2 %0, %1, %2, %0;" : "+l"(d) : "l"(a), "l"(b));
}

// ====================================================================
// Kernel 1: input projection GEMM with f32x2 accumulation (unchanged)
// ====================================================================
__global__ void __launch_bounds__(256) xproj_kernel(
    const float* __restrict__ A,
    const float* __restrict__ W,
    const float* __restrict__ bih,
    const float* __restrict__ bhh,
    float* __restrict__ C)
{
    __shared__ float As[16][132];
    __shared__ float Bs[16][132];

    const int tid = threadIdx.x;
    const int tx  = tid & 15;
    const int ty  = tid >> 4;
    const int m0  = blockIdx.y * 128;
    const int n0  = blockIdx.x * 128;

    u64 acc2[8][4];
#pragma unroll
    for (int i = 0; i < 8; i++)
#pragma unroll
        for (int p = 0; p < 4; p++) acc2[i][p] = 0ull;

    const float4* A4 = (const float4*)A;
    const float4* W4 = (const float4*)W;

    for (int k0 = 0; k0 < IDIM; k0 += 16) {
        const int kq = k0 >> 2;
#pragma unroll
        for (int q = 0; q < 2; q++) {
            int f  = q * 256 + tid;
            int r  = f >> 2;
            int c4 = f & 3;
            float4 av = A4[(size_t)(m0 + r) * 256 + kq + c4];
            As[c4 * 4 + 0][r] = av.x;
            As[c4 * 4 + 1][r] = av.y;
            As[c4 * 4 + 2][r] = av.z;
            As[c4 * 4 + 3][r] = av.w;
            float4 bv = W4[(size_t)(n0 + r) * 256 + kq + c4];
            Bs[c4 * 4 + 0][r] = bv.x;
            Bs[c4 * 4 + 1][r] = bv.y;
            Bs[c4 * 4 + 2][r] = bv.z;
            Bs[c4 * 4 + 3][r] = bv.w;
        }
        __syncthreads();

#pragma unroll
        for (int kk = 0; kk < 16; kk++) {
            float ra[8];
            *(float4*)&ra[0] = *(const float4*)&As[kk][ty * 4];
            *(float4*)&ra[4] = *(const float4*)&As[kk][64 + ty * 4];
            ulonglong2 rb0 = *(const ulonglong2*)&Bs[kk][tx * 4];
            ulonglong2 rb1 = *(const ulonglong2*)&Bs[kk][64 + tx * 4];
#pragma unroll
            for (int i = 0; i < 8; i++) {
                u64 rap = pack2(ra[i], ra[i]);
                fma2(acc2[i][0], rap, rb0.x);
                fma2(acc2[i][1], rap, rb0.y);
                fma2(acc2[i][2], rap, rb1.x);
                fma2(acc2[i][3], rap, rb1.y);
            }
        }
        __syncthreads();
    }

    float bsum[8];
#pragma unroll
    for (int j = 0; j < 8; j++) {
        int n = n0 + ((j < 4) ? (tx * 4 + j) : (64 + tx * 4 + (j - 4)));
        bsum[j] = bih[n] + bhh[n];
    }
#pragma unroll
    for (int i = 0; i < 8; i++) {
        int m = m0 + ((i < 4) ? (ty * 4 + i) : (64 + ty * 4 + (i - 4)));
        float c[8];
        unpack2(c[0], c[1], acc2[i][0]);
        unpack2(c[2], c[3], acc2[i][1]);
        unpack2(c[4], c[5], acc2[i][2]);
        unpack2(c[6], c[7], acc2[i][3]);
        float4 v0, v1;
        v0.x = c[0] + bsum[0]; v0.y = c[1] + bsum[1];
        v0.z = c[2] + bsum[2]; v0.w = c[3] + bsum[3];
        v1.x = c[4] + bsum[4]; v1.y = c[5] + bsum[5];
        v1.z = c[6] + bsum[6]; v1.w = c[7] + bsum[7];
        *(float4*)&C[(size_t)m * HDIM + n0 + tx * 4]      = v0;
        *(float4*)&C[(size_t)m * HDIM + n0 + 64 + tx * 4] = v1;
    }
}

// ====================================================================
// Kernel 2: persistent recurrence, v4 (K-split across warps).
//   128 CTAs = 4 groups x 32 CTAs, 256 threads (8 warps).
//   CTA tile: 16 batch x 32 neurons. Each warp computes partial sums
//   for ALL 512 outputs over K-chunk [w*128, w*128+128).
//   Thread register tile: 4j x 4b packed accumulators.
//   Epilogue: SMEM reduction over 8 warps + xp + relu + coalesced STG.
// ====================================================================
#define WSTR 1028                     // floats; WSTR/4=257 odd -> bank rotation
#define RSTR 33                       // partials: red[w][b*33 + j]
#define RED_WSZ (16 * RSTR)           // 528 floats per warp
#define SM_W   0
#define SM_H   (32 * WSTR)            // hsm base
#define SM_RED (48 * WSTR)            // red base
#define SM_XP  (48 * WSTR + 8 * RED_WSZ)
#define REC_SMEM_FLOATS (48 * WSTR + 8 * RED_WSZ + 512)
#define REC_SMEM_BYTES  (REC_SMEM_FLOATS * 4)

__device__ unsigned g_cnt[4];
__device__ volatile unsigned g_phase[4];

__global__ void __launch_bounds__(256, 1) rec_kernel(
    const float* __restrict__ h0,
    const float* __restrict__ Whh,
    float* out)
{
    extern __shared__ float sm[];
    float* Wsm = sm + SM_W;     // [32][WSTR]
    float* hsm = sm + SM_H;     // [16][WSTR]
    float* red = sm + SM_RED;   // [8][16*RSTR]
    float* xps = sm + SM_XP;    // [16][32]

    const int cta = blockIdx.x;
    const int grp = cta >> 5;        // 0..3 batch group
    const int gc  = cta & 31;        // 0..31 within group
    const int j0  = gc * 32;
    const int b0g = grp * 16;
    const int tid = threadIdx.x;
    const int w   = tid >> 5;        // warp: owns K chunk [w*128, +128)
    const int l   = tid & 31;
    const int jj  = l & 7;           // j rows: jj, jj+8, jj+16, jj+24
    const int bb  = l >> 3;          // b rows: bb, bb+4, bb+8, bb+12

    // ---- load W_hh rows [j0, j0+32) into SMEM once ----
    {
        const float4* W4 = (const float4*)Whh;
        for (int i = tid; i < 32 * 256; i += 256) {
            int r = i >> 8, c = i & 255;
            *(float4*)&Wsm[r * WSTR + c * 4] = W4[(size_t)(j0 + r) * 256 + c];
        }
    }

    // dot-loop base pointers (k-chunk offset w*128)
    const ulonglong2* wp[4];
    const ulonglong2* hp[4];
#pragma unroll
    for (int i = 0; i < 4; i++)
        wp[i] = (const ulonglong2*)(Wsm + (jj + 8 * i) * WSTR + w * 128);
#pragma unroll
    for (int m = 0; m < 4; m++)
        hp[m] = (const ulonglong2*)(hsm + (bb + 4 * m) * WSTR + w * 128);

    // reduce-phase mapping: thread -> (b, j-pair)
    const int rb = tid >> 4;          // 0..15
    const int rj = (tid & 15) * 2;    // 0..30 even
    const int bglob_r = b0g + rb;
    const int jglob_r = j0 + rj;

    unsigned my_phase = 0;

    for (int t = 0; t < S_LEN; t++) {
        // ---- stage h_{t-1} (16 rows x 1024 f32) into SMEM ----
        const float4* H4 = (t == 0)
            ? (const float4*)h0
            : (const float4*)(out + (size_t)(t - 1) * HDIM);
        const size_t rstride = (t == 0) ? 256u : (size_t)S_LEN * 256u;
#pragma unroll
        for (int q = 0; q < 16; q++) {
            int f = q * 256 + tid;            // 0..4095
            int r = f >> 8, c = f & 255;
            float4 v = __ldcv(&H4[(size_t)(b0g + r) * rstride + c]);
            *(float4*)&hsm[r * WSTR + c * 4] = v;
        }
        // ---- stage xp tile (16b x 32j) ----
        if (tid < 128) {
            int r = tid >> 3, c = tid & 7;    // row, float4-col
            const float4* src = (const float4*)
                (out + ((size_t)(b0g + r) * S_LEN + t) * HDIM + j0);
            *(float4*)&xps[r * 32 + c * 4] = src[c];
        }
        __syncthreads();

        // ---- K-chunk dot: 16 packed accumulators ----
        u64 acc[4][4];
#pragma unroll
        for (int m = 0; m < 4; m++)
#pragma unroll
            for (int i = 0; i < 4; i++) acc[m][i] = 0ull;

#pragma unroll 2
        for (int kq = 0; kq < 32; kq++) {     // 4 k per iter
            ulonglong2 wv[4], hv[4];
#pragma unroll
            for (int i = 0; i < 4; i++) wv[i] = wp[i][kq];
#pragma unroll
            for (int m = 0; m < 4; m++) hv[m] = hp[m][kq];
#pragma unroll
            for (int m = 0; m < 4; m++)
#pragma unroll
                for (int i = 0; i < 4; i++) {
                    fma2(acc[m][i], wv[i].x, hv[m].x);
                    fma2(acc[m][i], wv[i].y, hv[m].y);
                }
        }

        // ---- store partials to red[w][b*RSTR + j] ----
        float* rw = red + w * RED_WSZ;
#pragma unroll
        for (int m = 0; m < 4; m++)
#pragma unroll
            for (int i = 0; i < 4; i++) {
                float lo, hi;
                unpack2(lo, hi, acc[m][i]);
                rw[(bb + 4 * m) * RSTR + (jj + 8 * i)] = lo + hi;
            }
        __syncthreads();

        // ---- reduce 8 warps + xp + relu, store 2 outputs/thread ----
        float s0 = xps[rb * 32 + rj];
        float s1 = xps[rb * 32 + rj + 1];
#pragma unroll
        for (int ww = 0; ww < 8; ww++) {
            s0 += red[ww * RED_WSZ + rb * RSTR + rj];
            s1 += red[ww * RED_WSZ + rb * RSTR + rj + 1];
        }
        float h0v = fmaxf(s0, 0.0f);
        float h1v = fmaxf(s1, 0.0f);
        const size_t o = ((size_t)bglob_r * S_LEN + t) * HDIM + jglob_r;
        float2 hv2 = make_float2(h0v, h1v);
        *(float2*)&out[o] = hv2;
        if (t == S_LEN - 1) {
            *(float2*)&out[OUT_TAIL + (size_t)bglob_r * HDIM + jglob_r] = hv2;
        }

        // ---- group barrier (32 CTAs), sense-reversing ----
        __syncthreads();
        if (tid == 0) {
            __threadfence();
            unsigned old = atomicAdd(&g_cnt[grp], 1u);
            if (old == 31u) {
                atomicExch(&g_cnt[grp], 0u);
                __threadfence();
                g_phase[grp] = my_phase ^ 1u;
            } else {
                while (g_phase[grp] == my_phase) { __nanosleep(32); }
            }
            __threadfence();
        }
        my_phase ^= 1u;
        __syncthreads();
    }
}

// ====================================================================
// Launch
// ====================================================================
extern "C" void kernel_launch(void* const* d_in, const int* in_sizes, int n_in,
                              void* d_out, int out_size)
{
    const float* inputs = (const float*)d_in[0];   // [64,512,1024]
    const float* h0     = (const float*)d_in[1];   // [1,64,1024]
    const float* wih    = (const float*)d_in[2];   // [1024,1024]
    const float* whh    = (const float*)d_in[3];   // [1024,1024]
    const float* bih    = (const float*)d_in[4];   // [1024]
    const float* bhh    = (const float*)d_in[5];   // [1024]
    float* out = (float*)d_out;

    dim3 g1(HDIM / 128, M_TOT / 128);   // (8, 256)
    xproj_kernel<<<g1, 256>>>(inputs, wih, bih, bhh, out);

    cudaFuncSetAttribute(rec_kernel, cudaFuncAttributeMaxDynamicSharedMemorySize,
                         REC_SMEM_BYTES);
    rec_kernel<<<128, 256, REC_SMEM_BYTES>>>(h0, whh, out);
}

// round 7
// speedup vs baseline: 1.9120x; 1.0125x over previous
#include <cuda_runtime.h>

// Problem constants
#define S_LEN   512
#define HDIM    1024
#define BATCH   64
#define IDIM    1024
#define M_TOT   (BATCH * S_LEN)          // 32768
#define OUT_TAIL (BATCH * S_LEN * HDIM)  // offset of h_last region in d_out

typedef unsigned long long u64;

// ---- packed f32x2 helpers (SASS FFMA2 path, PTX-only) ----
__device__ __forceinline__ u64 pack2(float lo, float hi) {
    u64 r;
    asm("mov.b64 %0, {%1, %2};" : "=l"(r) : "f"(lo), "f"(hi));
    return r;
}
__device__ __forceinline__ void unpack2(float& lo, float& hi, u64 v) {
    asm("mov.b64 {%0, %1}, %2;" : "=f"(lo), "=f"(hi) : "l"(v));
}
__device__ __forceinline__ void fma2(u64& d, u64 a, u64 b) {
    asm("fma.rn.f32x2 %0, %1, %2, %0;" : "+l"(d) : "l"(a), "l"(b));
}

// ====================================================================
// Kernel 1: input projection GEMM with f32x2 accumulation (unchanged)
// ====================================================================
__global__ void __launch_bounds__(256) xproj_kernel(
    const float* __restrict__ A,
    const float* __restrict__ W,
    const float* __restrict__ bih,
    const float* __restrict__ bhh,
    float* __restrict__ C)
{
    __shared__ float As[16][132];
    __shared__ float Bs[16][132];

    const int tid = threadIdx.x;
    const int tx  = tid & 15;
    const int ty  = tid >> 4;
    const int m0  = blockIdx.y * 128;
    const int n0  = blockIdx.x * 128;

    u64 acc2[8][4];
#pragma unroll
    for (int i = 0; i < 8; i++)
#pragma unroll
        for (int p = 0; p < 4; p++) acc2[i][p] = 0ull;

    const float4* A4 = (const float4*)A;
    const float4* W4 = (const float4*)W;

    for (int k0 = 0; k0 < IDIM; k0 += 16) {
        const int kq = k0 >> 2;
#pragma unroll
        for (int q = 0; q < 2; q++) {
            int f  = q * 256 + tid;
            int r  = f >> 2;
            int c4 = f & 3;
            float4 av = A4[(size_t)(m0 + r) * 256 + kq + c4];
            As[c4 * 4 + 0][r] = av.x;
            As[c4 * 4 + 1][r] = av.y;
            As[c4 * 4 + 2][r] = av.z;
            As[c4 * 4 + 3][r] = av.w;
            float4 bv = W4[(size_t)(n0 + r) * 256 + kq + c4];
            Bs[c4 * 4 + 0][r] = bv.x;
            Bs[c4 * 4 + 1][r] = bv.y;
            Bs[c4 * 4 + 2][r] = bv.z;
            Bs[c4 * 4 + 3][r] = bv.w;
        }
        __syncthreads();

#pragma unroll
        for (int kk = 0; kk < 16; kk++) {
            float ra[8];
            *(float4*)&ra[0] = *(const float4*)&As[kk][ty * 4];
            *(float4*)&ra[4] = *(const float4*)&As[kk][64 + ty * 4];
            ulonglong2 rb0 = *(const ulonglong2*)&Bs[kk][tx * 4];
            ulonglong2 rb1 = *(const ulonglong2*)&Bs[kk][64 + tx * 4];
#pragma unroll
            for (int i = 0; i < 8; i++) {
                u64 rap = pack2(ra[i], ra[i]);
                fma2(acc2[i][0], rap, rb0.x);
                fma2(acc2[i][1], rap, rb0.y);
                fma2(acc2[i][2], rap, rb1.x);
                fma2(acc2[i][3], rap, rb1.y);
            }
        }
        __syncthreads();
    }

    float bsum[8];
#pragma unroll
    for (int j = 0; j < 8; j++) {
        int n = n0 + ((j < 4) ? (tx * 4 + j) : (64 + tx * 4 + (j - 4)));
        bsum[j] = bih[n] + bhh[n];
    }
#pragma unroll
    for (int i = 0; i < 8; i++) {
        int m = m0 + ((i < 4) ? (ty * 4 + i) : (64 + ty * 4 + (i - 4)));
        float c[8];
        unpack2(c[0], c[1], acc2[i][0]);
        unpack2(c[2], c[3], acc2[i][1]);
        unpack2(c[4], c[5], acc2[i][2]);
        unpack2(c[6], c[7], acc2[i][3]);
        float4 v0, v1;
        v0.x = c[0] + bsum[0]; v0.y = c[1] + bsum[1];
        v0.z = c[2] + bsum[2]; v0.w = c[3] + bsum[3];
        v1.x = c[4] + bsum[4]; v1.y = c[5] + bsum[5];
        v1.z = c[6] + bsum[6]; v1.w = c[7] + bsum[7];
        *(float4*)&C[(size_t)m * HDIM + n0 + tx * 4]      = v0;
        *(float4*)&C[(size_t)m * HDIM + n0 + 64 + tx * 4] = v1;
    }
}

// ====================================================================
// Kernel 2: persistent recurrence, v6 (= proven R5 structure +
//   MLP-batched staging + register xp + conflict-free partials).
//   128 CTAs = 4 groups x 32 CTAs, 256 threads (8 warps).
//   Warp w computes partials for all 512 outputs over K-chunk w*128.
// ====================================================================
#define WSTR 1028                     // hsm/Wsm row stride (floats)
#define RSTR 40                       // partials: (40*bb+8*i+jj) mod 32 covers all banks
#define RED_WSZ (16 * RSTR)           // 640 floats per warp
#define SM_H   (32 * WSTR)
#define SM_RED (48 * WSTR)
#define REC_SMEM_FLOATS (48 * WSTR + 8 * RED_WSZ)
#define REC_SMEM_BYTES  (REC_SMEM_FLOATS * 4)

__device__ unsigned g_cnt[4];
__device__ volatile unsigned g_phase[4];

__global__ void __launch_bounds__(256, 1) rec_kernel(
    const float* __restrict__ h0,
    const float* __restrict__ Whh,
    float* out)
{
    extern __shared__ float sm[];
    float* Wsm = sm;              // [32][WSTR]
    float* hsm = sm + SM_H;       // [16][WSTR]
    float* red = sm + SM_RED;     // [8][16*RSTR]

    const int cta = blockIdx.x;
    const int grp = cta >> 5;        // 0..3 batch group
    const int gc  = cta & 31;        // 0..31 within group
    const int j0  = gc * 32;
    const int b0g = grp * 16;
    const int tid = threadIdx.x;
    const int w   = tid >> 5;        // warp: owns K chunk [w*128, +128)
    const int l   = tid & 31;
    const int jj  = l & 7;           // j rows: jj, jj+8, jj+16, jj+24
    const int bb  = l >> 3;          // b rows: bb, bb+4, bb+8, bb+12

    // ---- load W_hh rows [j0, j0+32) into SMEM once ----
    {
        const float4* W4 = (const float4*)Whh;
        for (int i = tid; i < 32 * 256; i += 256) {
            int r = i >> 8, c = i & 255;
            *(float4*)&Wsm[r * WSTR + c * 4] = W4[(size_t)(j0 + r) * 256 + c];
        }
    }
    __syncthreads();

    // dot-loop base pointers (k-chunk offset w*128 floats)
    const ulonglong2* wp[4];
    const ulonglong2* hp[4];
#pragma unroll
    for (int i = 0; i < 4; i++)
        wp[i] = (const ulonglong2*)(Wsm + (jj + 8 * i) * WSTR + w * 128);
#pragma unroll
    for (int m = 0; m < 4; m++)
        hp[m] = (const ulonglong2*)(hsm + (bb + 4 * m) * WSTR + w * 128);

    // reduce-phase mapping: thread -> (b, j-pair)
    const int rb = tid >> 4;          // 0..15
    const int rj = (tid & 15) * 2;    // 0..30 even
    const int bglob_r = b0g + rb;
    const int jglob_r = j0 + rj;

    unsigned my_phase = 0;

    for (int t = 0; t < S_LEN; t++) {
        // ---- xp prefetch into registers (addr written only by this thread) ----
        const size_t oxp = ((size_t)bglob_r * S_LEN + t) * HDIM + jglob_r;
        float2 xv = *(const float2*)&out[oxp];

        // ---- stage h_{t-1}: 2 batches of (load 8 float4 -> regs, then STS) ----
        // thread handles float4 index f = batch*2048 + q*256 + tid
        const float4* H4 = (t == 0)
            ? (const float4*)h0
            : (const float4*)(out + (size_t)(t - 1) * HDIM);
        const size_t rstride = (t == 0) ? 256u : (size_t)S_LEN * 256u;
#pragma unroll
        for (int bt = 0; bt < 2; bt++) {
            float4 v[8];
#pragma unroll
            for (int q = 0; q < 8; q++) {
                int f = bt * 2048 + q * 256 + tid;   // 0..4095
                int r = f >> 8;
                int c = f & 255;
                v[q] = __ldcv(&H4[(size_t)(b0g + r) * rstride + c]);
            }
#pragma unroll
            for (int q = 0; q < 8; q++) {
                int f = bt * 2048 + q * 256 + tid;
                int r = f >> 8;
                int c = f & 255;
                *(float4*)&hsm[r * WSTR + c * 4] = v[q];
            }
        }
        __syncthreads();

        // ---- K-chunk dot: 16 packed accumulators ----
        u64 acc[4][4];
#pragma unroll
        for (int m = 0; m < 4; m++)
#pragma unroll
            for (int i = 0; i < 4; i++) acc[m][i] = 0ull;

#pragma unroll 2
        for (int kq = 0; kq < 32; kq++) {     // 4 k per iter
            ulonglong2 wv[4], hv[4];
#pragma unroll
            for (int i = 0; i < 4; i++) wv[i] = wp[i][kq];
#pragma unroll
            for (int m = 0; m < 4; m++) hv[m] = hp[m][kq];
#pragma unroll
            for (int m = 0; m < 4; m++)
#pragma unroll
                for (int i = 0; i < 4; i++) {
                    fma2(acc[m][i], wv[i].x, hv[m].x);
                    fma2(acc[m][i], wv[i].y, hv[m].y);
                }
        }

        // ---- store partials (conflict-free with RSTR=40) ----
        float* rw = red + w * RED_WSZ;
#pragma unroll
        for (int m = 0; m < 4; m++)
#pragma unroll
            for (int i = 0; i < 4; i++) {
                float lo, hi;
                unpack2(lo, hi, acc[m][i]);
                rw[(bb + 4 * m) * RSTR + (jj + 8 * i)] = lo + hi;
            }
        __syncthreads();

        // ---- reduce 8 warps + xp + relu; store 2 outputs/thread ----
        float s0 = xv.x, s1 = xv.y;
#pragma unroll
        for (int ww = 0; ww < 8; ww++) {
            float2 p = *(const float2*)&red[ww * RED_WSZ + rb * RSTR + rj];
            s0 += p.x;
            s1 += p.y;
        }
        float2 hv2 = make_float2(fmaxf(s0, 0.0f), fmaxf(s1, 0.0f));
        *(float2*)&out[oxp] = hv2;
        if (t == S_LEN - 1) {
            *(float2*)&out[OUT_TAIL + (size_t)bglob_r * HDIM + jglob_r] = hv2;
        }

        // ---- group barrier (32 CTAs), sense-reversing (proven) ----
        __syncthreads();
        if (tid == 0) {
            __threadfence();
            unsigned old = atomicAdd(&g_cnt[grp], 1u);
            if (old == 31u) {
                atomicExch(&g_cnt[grp], 0u);
                __threadfence();
                g_phase[grp] = my_phase ^ 1u;
            } else {
                while (g_phase[grp] == my_phase) { __nanosleep(32); }
            }
            __threadfence();
        }
        my_phase ^= 1u;
        __syncthreads();
    }
}

// ====================================================================
// Launch
// ====================================================================
extern "C" void kernel_launch(void* const* d_in, const int* in_sizes, int n_in,
                              void* d_out, int out_size)
{
    const float* inputs = (const float*)d_in[0];   // [64,512,1024]
    const float* h0     = (const float*)d_in[1];   // [1,64,1024]
    const float* wih    = (const float*)d_in[2];   // [1024,1024]
    const float* whh    = (const float*)d_in[3];   // [1024,1024]
    const float* bih    = (const float*)d_in[4];   // [1024]
    const float* bhh    = (const float*)d_in[5];   // [1024]
    float* out = (float*)d_out;

    dim3 g1(HDIM / 128, M_TOT / 128);   // (8, 256)
    xproj_kernel<<<g1, 256>>>(inputs, wih, bih, bhh, out);

    cudaFuncSetAttribute(rec_kernel, cudaFuncAttributeMaxDynamicSharedMemorySize,
                         REC_SMEM_BYTES);
    rec_kernel<<<128, 256, REC_SMEM_BYTES>>>(h0, whh, out);
}